// round 7
// baseline (speedup 1.0000x reference)
#include <cuda_runtime.h>
#include <cuda_bf16.h>
#include <math.h>
#include <stdint.h>

// Problem constants
#define B_   4
#define T_   2048
#define C_   2048
#define NH   16
#define NKV  4
#define HD_  128
#define QKVD ((NH + 2 * NKV) * HD_)   // 3072

// ---------------- scratch (device globals; no runtime allocation) ----------
__device__ float g_cos[T_ * (HD_ / 2)];
__device__ float g_sin[T_ * (HD_ / 2)];
__device__ __nv_bfloat16 g_xh[(size_t)B_ * T_ * C_];
__device__ __nv_bfloat16 g_xl[(size_t)B_ * T_ * C_];
__device__ __nv_bfloat16 g_yh[(size_t)B_ * T_ * C_];
__device__ __nv_bfloat16 g_yl[(size_t)B_ * T_ * C_];
__device__ __nv_bfloat16 g_wah[(size_t)QKVD * C_];
__device__ __nv_bfloat16 g_wal[(size_t)QKVD * C_];
__device__ __nv_bfloat16 g_wph[(size_t)C_ * C_];
__device__ __nv_bfloat16 g_wpl[(size_t)C_ * C_];
__device__ __nv_bfloat16 g_qh[(size_t)B_ * NH * T_ * HD_];
__device__ __nv_bfloat16 g_ql[(size_t)B_ * NH * T_ * HD_];
__device__ __nv_bfloat16 g_kh[(size_t)B_ * NKV * T_ * HD_];
__device__ __nv_bfloat16 g_kl[(size_t)B_ * NKV * T_ * HD_];
__device__ __nv_bfloat16 g_vh[(size_t)B_ * NKV * T_ * HD_];
__device__ __nv_bfloat16 g_vl[(size_t)B_ * NKV * T_ * HD_];

// ---------------- small PTX helpers ----------------------------------------
__device__ __forceinline__ uint32_t smem_u32(const void* p) {
    uint32_t a;
    asm("{ .reg .u64 t; cvta.to.shared.u64 t, %1; cvt.u32.u64 %0, t; }"
        : "=r"(a) : "l"(p));
    return a;
}
__device__ __forceinline__ void cpa16(uint32_t d, const void* g) {
    asm volatile("cp.async.cg.shared.global [%0], [%1], 16;" :: "r"(d), "l"(g));
}
__device__ __forceinline__ void cpa_commit() {
    asm volatile("cp.async.commit_group;" ::: "memory");
}
template <int N>
__device__ __forceinline__ void cpa_wait() {
    asm volatile("cp.async.wait_group %0;" :: "n"(N) : "memory");
}
__device__ __forceinline__ void ldsm_x4(uint32_t& r0, uint32_t& r1,
                                        uint32_t& r2, uint32_t& r3, uint32_t a) {
    asm volatile("ldmatrix.sync.aligned.m8n8.x4.shared.b16 {%0,%1,%2,%3}, [%4];"
                 : "=r"(r0), "=r"(r1), "=r"(r2), "=r"(r3) : "r"(a));
}
__device__ __forceinline__ void ldsm_x4_t(uint32_t& r0, uint32_t& r1,
                                          uint32_t& r2, uint32_t& r3, uint32_t a) {
    asm volatile("ldmatrix.sync.aligned.m8n8.x4.trans.shared.b16 {%0,%1,%2,%3}, [%4];"
                 : "=r"(r0), "=r"(r1), "=r"(r2), "=r"(r3) : "r"(a));
}
__device__ __forceinline__ void mma_bf16(float* c, const uint32_t* a,
                                         const uint32_t* b) {
    asm volatile(
        "mma.sync.aligned.m16n8k16.row.col.f32.bf16.bf16.f32 "
        "{%0,%1,%2,%3},{%4,%5,%6,%7},{%8,%9},{%0,%1,%2,%3};"
        : "+f"(c[0]), "+f"(c[1]), "+f"(c[2]), "+f"(c[3])
        : "r"(a[0]), "r"(a[1]), "r"(a[2]), "r"(a[3]), "r"(b[0]), "r"(b[1]));
}
__device__ __forceinline__ uint32_t packbf(float lo, float hi) {
    uint32_t r;
    asm("cvt.rn.bf16x2.f32 %0, %1, %2;" : "=r"(r) : "f"(hi), "f"(lo));
    return r;
}
__device__ __forceinline__ float bflo(uint32_t r) { return __uint_as_float(r << 16); }
__device__ __forceinline__ float bfhi(uint32_t r) { return __uint_as_float(r & 0xffff0000u); }

// ---------------- RoPE table -------------------------------------------------
__global__ void rope_table_kernel() {
    int idx = blockIdx.x * blockDim.x + threadIdx.x;
    if (idx >= T_ * 64) return;
    int t = idx / 64;
    int i = idx % 64;
    double inv = exp(-((double)i / 64.0) * log(10000.0));
    double ang = (double)t * inv;
    g_cos[idx] = (float)cos(ang);
    g_sin[idx] = (float)sin(ang);
}

// ---------------- combined fp32 -> bf16 hi/lo split -------------------------
#define NX4  (B_ * T_ * C_ / 4)
#define NWA4 (QKVD * C_ / 4)
#define NWP4 (C_ * C_ / 4)
__global__ void split_all_kernel(const float* __restrict__ x,
                                 const float* __restrict__ wa,
                                 const float* __restrict__ wp) {
    int i = blockIdx.x * blockDim.x + threadIdx.x;
    const float* src;
    __nv_bfloat16 *hi, *lo;
    int j;
    if (i < NX4) { src = x; hi = g_xh; lo = g_xl; j = i; }
    else if (i < NX4 + NWA4) { src = wa; hi = g_wah; lo = g_wal; j = i - NX4; }
    else if (i < NX4 + NWA4 + NWP4) { src = wp; hi = g_wph; lo = g_wpl; j = i - NX4 - NWA4; }
    else return;
    float4 v = ((const float4*)src)[j];
    float vv[4] = {v.x, v.y, v.z, v.w};
    __nv_bfloat16 h[4], l[4];
#pragma unroll
    for (int q = 0; q < 4; q++) {
        h[q] = __float2bfloat16_rn(vv[q]);
        l[q] = __float2bfloat16_rn(vv[q] - __bfloat162float(h[q]));
    }
    ((__nv_bfloat162*)hi)[2 * j]     = __halves2bfloat162(h[0], h[1]);
    ((__nv_bfloat162*)hi)[2 * j + 1] = __halves2bfloat162(h[2], h[3]);
    ((__nv_bfloat162*)lo)[2 * j]     = __halves2bfloat162(l[0], l[1]);
    ((__nv_bfloat162*)lo)[2 * j + 1] = __halves2bfloat162(l[2], l[3]);
}

// ---------------- fused epilogue store: RoPE + split + head-major scatter ---
__device__ __forceinline__ void rope_split_store(int row, int col,
                                                 float v0, float v1) {
    const int t = row & (T_ - 1);
    const int b = row >> 11;
    const int h = col >> 7;
    const int d = col & 127;
    if (h < NH + NKV) {
        const int i = d >> 1;
        float c = g_cos[t * 64 + i];
        float s = g_sin[t * 64 + i];
        float o0 = v0 * c - v1 * s;
        float o1 = v0 * s + v1 * c;
        v0 = o0; v1 = o1;
    }
    __nv_bfloat16 h0 = __float2bfloat16_rn(v0);
    __nv_bfloat16 h1 = __float2bfloat16_rn(v1);
    __nv_bfloat16 l0 = __float2bfloat16_rn(v0 - __bfloat162float(h0));
    __nv_bfloat16 l1 = __float2bfloat16_rn(v1 - __bfloat162float(h1));
    __nv_bfloat16 *dh, *dl;
    size_t off;
    if (h < NH) {
        dh = g_qh; dl = g_ql;
        off = ((size_t)(b * NH + h) * T_ + t) * HD_ + d;
    } else if (h < NH + NKV) {
        dh = g_kh; dl = g_kl;
        off = ((size_t)(b * NKV + (h - NH)) * T_ + t) * HD_ + d;
    } else {
        dh = g_vh; dl = g_vl;
        off = ((size_t)(b * NKV + (h - NH - NKV)) * T_ + t) * HD_ + d;
    }
    *(__nv_bfloat162*)(dh + off) = __halves2bfloat162(h0, h1);
    *(__nv_bfloat162*)(dl + off) = __halves2bfloat162(l0, l1);
}

// ---------------- mma.sync bf16x3 GEMM (NT), 3-stage pipeline ---------------
#define GPITCH 40
#define GTILE  (128 * GPITCH)
#define GSTAGE (4 * GTILE)
#define GEMM_SMEM (3 * GSTAGE * 2)

template <int EPI>
__global__ __launch_bounds__(256) void gemm_mma(
    const __nv_bfloat16* __restrict__ Ah, const __nv_bfloat16* __restrict__ Al,
    const __nv_bfloat16* __restrict__ Bh, const __nv_bfloat16* __restrict__ Bl,
    float* __restrict__ Cm, int M, int N, int K) {
    extern __shared__ __nv_bfloat16 smg[];
    const int tid = threadIdx.x;
    const int lane = tid & 31;
    const int w = tid >> 5;
    const int wm = w & 1;
    const int wn = w >> 1;
    const size_t bm = (size_t)blockIdx.y * 128;
    const size_t bn = (size_t)blockIdx.x * 128;
    const uint32_t sbase = smem_u32(smg);

    float acc[4][4][4];
#pragma unroll
    for (int i = 0; i < 4; i++)
#pragma unroll
        for (int j = 0; j < 4; j++)
#pragma unroll
            for (int q = 0; q < 4; q++) acc[i][j][q] = 0.0f;

    const int NC = K >> 5;

    auto load_stage = [&](int chunk) {
        uint32_t st = sbase + (uint32_t)(chunk % 3) * (GSTAGE * 2);
        const int k0 = chunk << 5;
#pragma unroll
        for (int s = 0; s < 8; s++) {
            int idx = s * 256 + tid;
            int tile = idx >> 9;
            int row = (idx >> 2) & 127;
            int ch = idx & 3;
            uint32_t dst = st + (uint32_t)(tile * GTILE + row * GPITCH + ch * 8) * 2;
            const __nv_bfloat16* src;
            if (tile == 0)      src = Ah + (bm + row) * (size_t)K + k0 + ch * 8;
            else if (tile == 1) src = Al + (bm + row) * (size_t)K + k0 + ch * 8;
            else if (tile == 2) src = Bh + (bn + row) * (size_t)K + k0 + ch * 8;
            else                src = Bl + (bn + row) * (size_t)K + k0 + ch * 8;
            cpa16(dst, src);
        }
        cpa_commit();
    };

    load_stage(0);
    load_stage(1);
    load_stage(2);

    for (int c = 0; c < NC; c++) {
        if (c + 2 < NC) cpa_wait<2>();
        else if (c + 1 < NC) cpa_wait<1>();
        else cpa_wait<0>();
        __syncthreads();

        uint32_t st = sbase + (uint32_t)(c % 3) * (GSTAGE * 2);
        uint32_t aHh = st;
        uint32_t aLl = st + (uint32_t)GTILE * 2;
        uint32_t bHh = st + (uint32_t)(2 * GTILE) * 2;
        uint32_t bLl = st + (uint32_t)(3 * GTILE) * 2;

#pragma unroll
        for (int ks = 0; ks < 2; ks++) {
            const int k0 = ks * 16;
            uint32_t ah[4][4], al[4][4];
            {
                int mrow = wm * 64 + (lane & 7) + ((lane >> 3) & 1) * 8;
                int kcol = k0 + (lane >> 4) * 8;
                uint32_t off = (uint32_t)(mrow * GPITCH + kcol) * 2;
#pragma unroll
                for (int mi = 0; mi < 4; mi++) {
                    uint32_t ao = off + (uint32_t)(mi * 16 * GPITCH) * 2;
                    ldsm_x4(ah[mi][0], ah[mi][1], ah[mi][2], ah[mi][3], aHh + ao);
                    ldsm_x4(al[mi][0], al[mi][1], al[mi][2], al[mi][3], aLl + ao);
                }
            }
            uint32_t bh[2][4], bl[2][4];
            {
                int nrow = wn * 32 + ((lane >> 4) << 3) + (lane & 7);
                int kcol = k0 + ((lane >> 3) & 1) * 8;
                uint32_t off = (uint32_t)(nrow * GPITCH + kcol) * 2;
#pragma unroll
                for (int p = 0; p < 2; p++) {
                    uint32_t bo = off + (uint32_t)(p * 16 * GPITCH) * 2;
                    ldsm_x4(bh[p][0], bh[p][1], bh[p][2], bh[p][3], bHh + bo);
                    ldsm_x4(bl[p][0], bl[p][1], bl[p][2], bl[p][3], bLl + bo);
                }
            }
#pragma unroll
            for (int mi = 0; mi < 4; mi++)
#pragma unroll
                for (int ni = 0; ni < 4; ni++)
                    mma_bf16(acc[mi][ni], ah[mi], &bh[ni >> 1][(ni & 1) * 2]);
#pragma unroll
            for (int mi = 0; mi < 4; mi++)
#pragma unroll
                for (int ni = 0; ni < 4; ni++)
                    mma_bf16(acc[mi][ni], ah[mi], &bl[ni >> 1][(ni & 1) * 2]);
#pragma unroll
            for (int mi = 0; mi < 4; mi++)
#pragma unroll
                for (int ni = 0; ni < 4; ni++)
                    mma_bf16(acc[mi][ni], al[mi], &bh[ni >> 1][(ni & 1) * 2]);
        }
        __syncthreads();
        if (c + 3 < NC) load_stage(c + 3);
    }

#pragma unroll
    for (int mi = 0; mi < 4; mi++) {
        int r0 = (int)(bm + wm * 64 + mi * 16 + (lane >> 2));
#pragma unroll
        for (int ni = 0; ni < 4; ni++) {
            int col = (int)(bn + wn * 32 + ni * 8 + 2 * (lane & 3));
            if (EPI == 0) {
                *(float2*)(Cm + (size_t)r0 * N + col) =
                    make_float2(acc[mi][ni][0], acc[mi][ni][1]);
                *(float2*)(Cm + (size_t)(r0 + 8) * N + col) =
                    make_float2(acc[mi][ni][2], acc[mi][ni][3]);
            } else {
                rope_split_store(r0, col, acc[mi][ni][0], acc[mi][ni][1]);
                rope_split_store(r0 + 8, col, acc[mi][ni][2], acc[mi][ni][3]);
            }
        }
    }
}

// ---------------- tensor-core flash attention (causal, GQA) ------------------
// 64 q-rows per CTA, 4 warps (16 rows each), KV tile 32 rows, 2 CTAs/SM.
#define FQR 64
#define FKT 32
#define FP 136
#define FQT_E (FQR * FP)           // 8704 elems per Q copy
#define FKV_E (FKT * FP)           // 4352 elems per kv tile
#define FSTG_E (4 * FKV_E)         // 17408 elems per stage
#define FLASH_SMEM ((2 * FQT_E + 2 * FSTG_E) * 2)   // 104448 B

__global__ __launch_bounds__(128) void flash_mma() {
    extern __shared__ __nv_bfloat16 fsm[];
    const uint32_t sb = smem_u32(fsm);
    const int tid = threadIdx.x;
    const int lane = tid & 31;
    const int w = tid >> 5;                         // 0..3
    const int qt = (int)(gridDim.x - 1 - blockIdx.x);   // 0..31, longest first
    const int h = blockIdx.y;
    const int b = blockIdx.z;
    const int kvh = h >> 2;
    const int qbase = qt * FQR;
    const int nkv = 2 * qt + 2;

    const __nv_bfloat16* qhp = g_qh + ((size_t)(b * NH + h) * T_ + qbase) * HD_;
    const __nv_bfloat16* qlp = g_ql + ((size_t)(b * NH + h) * T_ + qbase) * HD_;
    const __nv_bfloat16* khp = g_kh + (size_t)(b * NKV + kvh) * T_ * HD_;
    const __nv_bfloat16* klp = g_kl + (size_t)(b * NKV + kvh) * T_ * HD_;
    const __nv_bfloat16* vhp = g_vh + (size_t)(b * NKV + kvh) * T_ * HD_;
    const __nv_bfloat16* vlp = g_vl + (size_t)(b * NKV + kvh) * T_ * HD_;

    // Q load (hi+lo): 2048 16B chunks over 128 threads
#pragma unroll
    for (int s = 0; s < 16; s++) {
        int idx = s * 128 + tid;
        int half = idx >> 10;
        int rem = idx & 1023;
        int row = rem >> 4;       // 0..63
        int ch = rem & 15;
        uint32_t dst = sb + (uint32_t)(half * FQT_E + row * FP) * 2 + ch * 16;
        const __nv_bfloat16* src = (half ? qlp : qhp) + (size_t)row * HD_ + ch * 8;
        cpa16(dst, src);
    }

    auto load_kv = [&](int ki) {
        int kv0 = ki * FKT;
        uint32_t stb = sb + (uint32_t)(2 * FQT_E + (ki & 1) * FSTG_E) * 2;
#pragma unroll
        for (int s = 0; s < 16; s++) {
            int idx = s * 128 + tid;
            int tile = idx >> 9;      // 512 chunks per tile
            int rem = idx & 511;
            int row = rem >> 4;       // 0..31
            int ch = rem & 15;
            uint32_t dst = stb + (uint32_t)(tile * FKV_E + row * FP) * 2 + ch * 16;
            const __nv_bfloat16* base =
                (tile == 0) ? khp : (tile == 1) ? klp : (tile == 2) ? vhp : vlp;
            cpa16(dst, base + (size_t)(kv0 + row) * HD_ + ch * 8);
        }
        cpa_commit();
    };

    load_kv(0);   // group 1: Q + kv0
    load_kv(1);   // group 2: kv1

    float O[16][4];
#pragma unroll
    for (int i = 0; i < 16; i++)
#pragma unroll
        for (int c = 0; c < 4; c++) O[i][c] = 0.0f;
    float m_i[2] = {-1e30f, -1e30f};
    float l_i[2] = {0.0f, 0.0f};
    const float scale = 0.08838834764831843f;

    const int mrow = w * 16 + (lane & 7) + ((lane >> 3) & 1) * 8;
    const int kcA = (lane >> 4) * 8;
    const int nrowK = ((lane >> 4) << 3) + (lane & 7);
    const int kcK = ((lane >> 3) & 1) * 8;
    const int krowV = (lane & 7) + ((lane >> 3) & 1) * 8;
    const int ncV = lane >> 4;
    const int row_in_w = lane >> 2;
    const int rowg0 = qbase + w * 16 + row_in_w;

    for (int ki = 0; ki < nkv; ki++) {
        if (ki + 1 < nkv) cpa_wait<1>(); else cpa_wait<0>();
        __syncthreads();

        const bool active = (ki * FKT <= qbase + w * 16 + 15);
        if (active) {
            uint32_t stb = sb + (uint32_t)(2 * FQT_E + (ki & 1) * FSTG_E) * 2;
            uint32_t kh_b = stb;
            uint32_t kl_b = stb + (uint32_t)FKV_E * 2;
            uint32_t vh_b = stb + (uint32_t)(2 * FKV_E) * 2;
            uint32_t vl_b = stb + (uint32_t)(3 * FKV_E) * 2;

            // ---- S = Q K^T (m16 x n32 per warp, K=128)
            float sacc[4][4];
#pragma unroll
            for (int i = 0; i < 4; i++)
#pragma unroll
                for (int c = 0; c < 4; c++) sacc[i][c] = 0.0f;

#pragma unroll
            for (int ks = 0; ks < 8; ks++) {
                uint32_t ah[4], al[4];
                uint32_t aoff = (uint32_t)(mrow * FP + ks * 16 + kcA) * 2;
                ldsm_x4(ah[0], ah[1], ah[2], ah[3], sb + aoff);
                ldsm_x4(al[0], al[1], al[2], al[3], sb + (uint32_t)FQT_E * 2 + aoff);
                uint32_t kh4[2][4], kl4[2][4];
                uint32_t koff = (uint32_t)(nrowK * FP + ks * 16 + kcK) * 2;
#pragma unroll
                for (int p = 0; p < 2; p++) {
                    uint32_t bo = koff + (uint32_t)(p * 16 * FP) * 2;
                    ldsm_x4(kh4[p][0], kh4[p][1], kh4[p][2], kh4[p][3], kh_b + bo);
                    ldsm_x4(kl4[p][0], kl4[p][1], kl4[p][2], kl4[p][3], kl_b + bo);
                }
#pragma unroll
                for (int p = 0; p < 2; p++) {
                    mma_bf16(sacc[2 * p], ah, &kh4[p][0]);
                    mma_bf16(sacc[2 * p + 1], ah, &kh4[p][2]);
                }
#pragma unroll
                for (int p = 0; p < 2; p++) {
                    mma_bf16(sacc[2 * p], ah, &kl4[p][0]);
                    mma_bf16(sacc[2 * p + 1], ah, &kl4[p][2]);
                }
#pragma unroll
                for (int p = 0; p < 2; p++) {
                    mma_bf16(sacc[2 * p], al, &kh4[p][0]);
                    mma_bf16(sacc[2 * p + 1], al, &kh4[p][2]);
                }
            }

            const int kv0 = ki * FKT;
            if (ki >= 2 * qt) {
#pragma unroll
                for (int ni = 0; ni < 4; ni++)
#pragma unroll
                    for (int c = 0; c < 4; c++) {
                        int colg = kv0 + ni * 8 + 2 * (lane & 3) + (c & 1);
                        int rowg = rowg0 + ((c >> 1) << 3);
                        sacc[ni][c] = (colg <= rowg) ? sacc[ni][c] * scale : -1e30f;
                    }
            } else {
#pragma unroll
                for (int ni = 0; ni < 4; ni++)
#pragma unroll
                    for (int c = 0; c < 4; c++) sacc[ni][c] *= scale;
            }

            float mx0 = -1e30f, mx1 = -1e30f;
#pragma unroll
            for (int ni = 0; ni < 4; ni++) {
                mx0 = fmaxf(mx0, fmaxf(sacc[ni][0], sacc[ni][1]));
                mx1 = fmaxf(mx1, fmaxf(sacc[ni][2], sacc[ni][3]));
            }
#pragma unroll
            for (int off = 1; off <= 2; off <<= 1) {
                mx0 = fmaxf(mx0, __shfl_xor_sync(0xffffffffu, mx0, off));
                mx1 = fmaxf(mx1, __shfl_xor_sync(0xffffffffu, mx1, off));
            }
            float mn0 = fmaxf(m_i[0], mx0);
            float mn1 = fmaxf(m_i[1], mx1);
            float cr0 = __expf(m_i[0] - mn0);
            float cr1 = __expf(m_i[1] - mn1);
            m_i[0] = mn0; m_i[1] = mn1;
            float sm0 = 0.0f, sm1 = 0.0f;
#pragma unroll
            for (int ni = 0; ni < 4; ni++) {
                float p0 = __expf(sacc[ni][0] - mn0);
                float p1 = __expf(sacc[ni][1] - mn0);
                float p2 = __expf(sacc[ni][2] - mn1);
                float p3 = __expf(sacc[ni][3] - mn1);
                sacc[ni][0] = p0; sacc[ni][1] = p1;
                sacc[ni][2] = p2; sacc[ni][3] = p3;
                sm0 += p0 + p1;
                sm1 += p2 + p3;
            }
#pragma unroll
            for (int off = 1; off <= 2; off <<= 1) {
                sm0 += __shfl_xor_sync(0xffffffffu, sm0, off);
                sm1 += __shfl_xor_sync(0xffffffffu, sm1, off);
            }
            l_i[0] = l_i[0] * cr0 + sm0;
            l_i[1] = l_i[1] * cr1 + sm1;
#pragma unroll
            for (int ni = 0; ni < 16; ni++) {
                O[ni][0] *= cr0; O[ni][1] *= cr0;
                O[ni][2] *= cr1; O[ni][3] *= cr1;
            }

            // ---- O += P V (m16 x n128, k32)
#pragma unroll
            for (int kt = 0; kt < 2; kt++) {
                uint32_t aP[4], aPl[4];
                {
                    float p0 = sacc[2 * kt][0], p1 = sacc[2 * kt][1];
                    float p2 = sacc[2 * kt][2], p3 = sacc[2 * kt][3];
                    float q0 = sacc[2 * kt + 1][0], q1 = sacc[2 * kt + 1][1];
                    float q2 = sacc[2 * kt + 1][2], q3 = sacc[2 * kt + 1][3];
                    aP[0] = packbf(p0, p1);
                    aP[1] = packbf(p2, p3);
                    aP[2] = packbf(q0, q1);
                    aP[3] = packbf(q2, q3);
                    aPl[0] = packbf(p0 - bflo(aP[0]), p1 - bfhi(aP[0]));
                    aPl[1] = packbf(p2 - bflo(aP[1]), p3 - bfhi(aP[1]));
                    aPl[2] = packbf(q0 - bflo(aP[2]), q1 - bfhi(aP[2]));
                    aPl[3] = packbf(q2 - bflo(aP[3]), q3 - bfhi(aP[3]));
                }
#pragma unroll
                for (int g = 0; g < 4; g++) {
                    uint32_t vh0[4], vl0[4], vh1[4], vl1[4];
                    uint32_t voff0 =
                        (uint32_t)((kt * 16 + krowV) * FP + (4 * g + ncV) * 8) * 2;
                    uint32_t voff1 =
                        (uint32_t)((kt * 16 + krowV) * FP + (4 * g + 2 + ncV) * 8) * 2;
                    ldsm_x4_t(vh0[0], vh0[1], vh0[2], vh0[3], vh_b + voff0);
                    ldsm_x4_t(vl0[0], vl0[1], vl0[2], vl0[3], vl_b + voff0);
                    ldsm_x4_t(vh1[0], vh1[1], vh1[2], vh1[3], vh_b + voff1);
                    ldsm_x4_t(vl1[0], vl1[1], vl1[2], vl1[3], vl_b + voff1);
                    mma_bf16(O[4 * g + 0], aP, vh0);
                    mma_bf16(O[4 * g + 1], aP, vh0 + 2);
                    mma_bf16(O[4 * g + 2], aP, vh1);
                    mma_bf16(O[4 * g + 3], aP, vh1 + 2);
                    mma_bf16(O[4 * g + 0], aP, vl0);
                    mma_bf16(O[4 * g + 1], aP, vl0 + 2);
                    mma_bf16(O[4 * g + 2], aP, vl1);
                    mma_bf16(O[4 * g + 3], aP, vl1 + 2);
                    mma_bf16(O[4 * g + 0], aPl, vh0);
                    mma_bf16(O[4 * g + 1], aPl, vh0 + 2);
                    mma_bf16(O[4 * g + 2], aPl, vh1);
                    mma_bf16(O[4 * g + 3], aPl, vh1 + 2);
                }
            }
        }
        __syncthreads();
        if (ki + 2 < nkv) load_kv(ki + 2);
    }

    // ---- epilogue: O / l -> bf16 hi/lo (g_yh, g_yl) directly
    float inv0 = 1.0f / l_i[0];
    float inv1 = 1.0f / l_i[1];
    const int rg0 = qbase + w * 16 + row_in_w;
#pragma unroll
    for (int ni = 0; ni < 16; ni++) {
        int col = h * HD_ + ni * 8 + 2 * (lane & 3);
        size_t o0 = ((size_t)b * T_ + rg0) * C_ + col;
        size_t o1 = ((size_t)b * T_ + rg0 + 8) * C_ + col;
        float v0 = O[ni][0] * inv0, v1 = O[ni][1] * inv0;
        float v2 = O[ni][2] * inv1, v3 = O[ni][3] * inv1;
        __nv_bfloat16 h0 = __float2bfloat16_rn(v0);
        __nv_bfloat16 h1 = __float2bfloat16_rn(v1);
        __nv_bfloat16 h2 = __float2bfloat16_rn(v2);
        __nv_bfloat16 h3 = __float2bfloat16_rn(v3);
        *(__nv_bfloat162*)(g_yh + o0) = __halves2bfloat162(h0, h1);
        *(__nv_bfloat162*)(g_yh + o1) = __halves2bfloat162(h2, h3);
        *(__nv_bfloat162*)(g_yl + o0) = __halves2bfloat162(
            __float2bfloat16_rn(v0 - __bfloat162float(h0)),
            __float2bfloat16_rn(v1 - __bfloat162float(h1)));
        *(__nv_bfloat162*)(g_yl + o1) = __halves2bfloat162(
            __float2bfloat16_rn(v2 - __bfloat162float(h2)),
            __float2bfloat16_rn(v3 - __bfloat162float(h3)));
    }
}

// ---------------- driver ----------------------------------------------------
extern "C" void kernel_launch(void* const* d_in, const int* in_sizes, int n_in,
                              void* d_out, int out_size) {
    const float* x = nullptr;
    const float* w_attn = nullptr;
    const float* w_proj = nullptr;
    for (int i = 0; i < n_in; i++) {
        if (in_sizes[i] == B_ * T_ * C_) x = (const float*)d_in[i];
        else if (in_sizes[i] == QKVD * C_) w_attn = (const float*)d_in[i];
        else if (in_sizes[i] == C_ * C_) w_proj = (const float*)d_in[i];
    }
    float* out = (float*)d_out;

    __nv_bfloat16 *xh, *xl, *yh, *yl, *wah, *wal, *wph, *wpl;
    cudaGetSymbolAddress((void**)&xh, g_xh);
    cudaGetSymbolAddress((void**)&xl, g_xl);
    cudaGetSymbolAddress((void**)&yh, g_yh);
    cudaGetSymbolAddress((void**)&yl, g_yl);
    cudaGetSymbolAddress((void**)&wah, g_wah);
    cudaGetSymbolAddress((void**)&wal, g_wal);
    cudaGetSymbolAddress((void**)&wph, g_wph);
    cudaGetSymbolAddress((void**)&wpl, g_wpl);

    cudaFuncSetAttribute(gemm_mma<0>, cudaFuncAttributeMaxDynamicSharedMemorySize,
                         GEMM_SMEM);
    cudaFuncSetAttribute(gemm_mma<1>, cudaFuncAttributeMaxDynamicSharedMemorySize,
                         GEMM_SMEM);
    cudaFuncSetAttribute(flash_mma, cudaFuncAttributeMaxDynamicSharedMemorySize,
                         FLASH_SMEM);

    // 1: RoPE table
    rope_table_kernel<<<(T_ * 64 + 255) / 256, 256>>>();

    // 2: combined splits (x, w_attn, w_proj)
    {
        int total = NX4 + NWA4 + NWP4;
        split_all_kernel<<<(total + 255) / 256, 256>>>(x, w_attn, w_proj);
    }

    // 3: GEMM1 (fused RoPE/split/scatter epilogue)
    {
        dim3 grid(QKVD / 128, (B_ * T_) / 128);
        gemm_mma<1><<<grid, 256, GEMM_SMEM>>>(xh, xl, wah, wal, nullptr,
                                              B_ * T_, QKVD, C_);
    }

    // 4: tensor-core flash attention -> g_yh/g_yl  (ncu capture slot)
    {
        dim3 grid(T_ / FQR, NH, B_);
        flash_mma<<<grid, 128, FLASH_SMEM>>>();
    }

    // 5: GEMM2: out = y @ w_proj^T
    {
        dim3 grid(C_ / 128, (B_ * T_) / 128);
        gemm_mma<0><<<grid, 256, GEMM_SMEM>>>(yh, yl, wph, wpl, out,
                                              B_ * T_, C_, C_);
    }
}

// round 8
// speedup vs baseline: 1.1636x; 1.1636x over previous
#include <cuda_runtime.h>
#include <cuda_bf16.h>
#include <math.h>
#include <stdint.h>

// Problem constants
#define B_   4
#define T_   2048
#define C_   2048
#define NH   16
#define NKV  4
#define HD_  128
#define QKVD ((NH + 2 * NKV) * HD_)   // 3072

// ---------------- scratch (device globals; no runtime allocation) ----------
__device__ float g_cos[T_ * (HD_ / 2)];
__device__ float g_sin[T_ * (HD_ / 2)];
__device__ __nv_bfloat16 g_xh[(size_t)B_ * T_ * C_];
__device__ __nv_bfloat16 g_xl[(size_t)B_ * T_ * C_];
__device__ __nv_bfloat16 g_yh[(size_t)B_ * T_ * C_];
__device__ __nv_bfloat16 g_yl[(size_t)B_ * T_ * C_];
__device__ __nv_bfloat16 g_wah[(size_t)QKVD * C_];
__device__ __nv_bfloat16 g_wal[(size_t)QKVD * C_];
__device__ __nv_bfloat16 g_wph[(size_t)C_ * C_];
__device__ __nv_bfloat16 g_wpl[(size_t)C_ * C_];
__device__ __nv_bfloat16 g_qh[(size_t)B_ * NH * T_ * HD_];
__device__ __nv_bfloat16 g_ql[(size_t)B_ * NH * T_ * HD_];
__device__ __nv_bfloat16 g_kh[(size_t)B_ * NKV * T_ * HD_];
__device__ __nv_bfloat16 g_kl[(size_t)B_ * NKV * T_ * HD_];
__device__ __nv_bfloat16 g_vh[(size_t)B_ * NKV * T_ * HD_];
__device__ __nv_bfloat16 g_vl[(size_t)B_ * NKV * T_ * HD_];

// ---------------- small PTX helpers ----------------------------------------
__device__ __forceinline__ uint32_t smem_u32(const void* p) {
    uint32_t a;
    asm("{ .reg .u64 t; cvta.to.shared.u64 t, %1; cvt.u32.u64 %0, t; }"
        : "=r"(a) : "l"(p));
    return a;
}
__device__ __forceinline__ void cpa16(uint32_t d, const void* g) {
    asm volatile("cp.async.cg.shared.global [%0], [%1], 16;" :: "r"(d), "l"(g));
}
__device__ __forceinline__ void cpa_commit() {
    asm volatile("cp.async.commit_group;" ::: "memory");
}
template <int N>
__device__ __forceinline__ void cpa_wait() {
    asm volatile("cp.async.wait_group %0;" :: "n"(N) : "memory");
}
__device__ __forceinline__ void ldsm_x4(uint32_t& r0, uint32_t& r1,
                                        uint32_t& r2, uint32_t& r3, uint32_t a) {
    asm volatile("ldmatrix.sync.aligned.m8n8.x4.shared.b16 {%0,%1,%2,%3}, [%4];"
                 : "=r"(r0), "=r"(r1), "=r"(r2), "=r"(r3) : "r"(a));
}
__device__ __forceinline__ void ldsm_x4_t(uint32_t& r0, uint32_t& r1,
                                          uint32_t& r2, uint32_t& r3, uint32_t a) {
    asm volatile("ldmatrix.sync.aligned.m8n8.x4.trans.shared.b16 {%0,%1,%2,%3}, [%4];"
                 : "=r"(r0), "=r"(r1), "=r"(r2), "=r"(r3) : "r"(a));
}
__device__ __forceinline__ void mma_bf16(float* c, const uint32_t* a,
                                         const uint32_t* b) {
    asm volatile(
        "mma.sync.aligned.m16n8k16.row.col.f32.bf16.bf16.f32 "
        "{%0,%1,%2,%3},{%4,%5,%6,%7},{%8,%9},{%0,%1,%2,%3};"
        : "+f"(c[0]), "+f"(c[1]), "+f"(c[2]), "+f"(c[3])
        : "r"(a[0]), "r"(a[1]), "r"(a[2]), "r"(a[3]), "r"(b[0]), "r"(b[1]));
}
__device__ __forceinline__ uint32_t packbf(float lo, float hi) {
    uint32_t r;
    asm("cvt.rn.bf16x2.f32 %0, %1, %2;" : "=r"(r) : "f"(hi), "f"(lo));
    return r;
}
__device__ __forceinline__ float bflo(uint32_t r) { return __uint_as_float(r << 16); }
__device__ __forceinline__ float bfhi(uint32_t r) { return __uint_as_float(r & 0xffff0000u); }

// ---------------- RoPE table -------------------------------------------------
__global__ void rope_table_kernel() {
    int idx = blockIdx.x * blockDim.x + threadIdx.x;
    if (idx >= T_ * 64) return;
    int t = idx / 64;
    int i = idx % 64;
    double inv = exp(-((double)i / 64.0) * log(10000.0));
    double ang = (double)t * inv;
    g_cos[idx] = (float)cos(ang);
    g_sin[idx] = (float)sin(ang);
}

// ---------------- combined fp32 -> bf16 hi/lo split -------------------------
#define NX4  (B_ * T_ * C_ / 4)
#define NWA4 (QKVD * C_ / 4)
#define NWP4 (C_ * C_ / 4)
__global__ void split_all_kernel(const float* __restrict__ x,
                                 const float* __restrict__ wa,
                                 const float* __restrict__ wp) {
    int i = blockIdx.x * blockDim.x + threadIdx.x;
    const float* src;
    __nv_bfloat16 *hi, *lo;
    int j;
    if (i < NX4) { src = x; hi = g_xh; lo = g_xl; j = i; }
    else if (i < NX4 + NWA4) { src = wa; hi = g_wah; lo = g_wal; j = i - NX4; }
    else if (i < NX4 + NWA4 + NWP4) { src = wp; hi = g_wph; lo = g_wpl; j = i - NX4 - NWA4; }
    else return;
    float4 v = ((const float4*)src)[j];
    float vv[4] = {v.x, v.y, v.z, v.w};
    __nv_bfloat16 h[4], l[4];
#pragma unroll
    for (int q = 0; q < 4; q++) {
        h[q] = __float2bfloat16_rn(vv[q]);
        l[q] = __float2bfloat16_rn(vv[q] - __bfloat162float(h[q]));
    }
    ((__nv_bfloat162*)hi)[2 * j]     = __halves2bfloat162(h[0], h[1]);
    ((__nv_bfloat162*)hi)[2 * j + 1] = __halves2bfloat162(h[2], h[3]);
    ((__nv_bfloat162*)lo)[2 * j]     = __halves2bfloat162(l[0], l[1]);
    ((__nv_bfloat162*)lo)[2 * j + 1] = __halves2bfloat162(l[2], l[3]);
}

// ---------------- fused epilogue store: RoPE + split + head-major scatter ---
__device__ __forceinline__ void rope_split_store(int row, int col,
                                                 float v0, float v1) {
    const int t = row & (T_ - 1);
    const int b = row >> 11;
    const int h = col >> 7;
    const int d = col & 127;
    if (h < NH + NKV) {
        const int i = d >> 1;
        float c = g_cos[t * 64 + i];
        float s = g_sin[t * 64 + i];
        float o0 = v0 * c - v1 * s;
        float o1 = v0 * s + v1 * c;
        v0 = o0; v1 = o1;
    }
    __nv_bfloat16 h0 = __float2bfloat16_rn(v0);
    __nv_bfloat16 h1 = __float2bfloat16_rn(v1);
    __nv_bfloat16 l0 = __float2bfloat16_rn(v0 - __bfloat162float(h0));
    __nv_bfloat16 l1 = __float2bfloat16_rn(v1 - __bfloat162float(h1));
    __nv_bfloat16 *dh, *dl;
    size_t off;
    if (h < NH) {
        dh = g_qh; dl = g_ql;
        off = ((size_t)(b * NH + h) * T_ + t) * HD_ + d;
    } else if (h < NH + NKV) {
        dh = g_kh; dl = g_kl;
        off = ((size_t)(b * NKV + (h - NH)) * T_ + t) * HD_ + d;
    } else {
        dh = g_vh; dl = g_vl;
        off = ((size_t)(b * NKV + (h - NH - NKV)) * T_ + t) * HD_ + d;
    }
    *(__nv_bfloat162*)(dh + off) = __halves2bfloat162(h0, h1);
    *(__nv_bfloat162*)(dl + off) = __halves2bfloat162(l0, l1);
}

// ---------------- mma.sync bf16x3 GEMM (NT), 2-stage (R6-validated) ---------
#define GPITCH 40
#define GTILE  (128 * GPITCH)
#define GSTAGE (4 * GTILE)
#define GEMM_SMEM (2 * GSTAGE * 2)

template <int EPI>
__global__ __launch_bounds__(256) void gemm_mma(
    const __nv_bfloat16* __restrict__ Ah, const __nv_bfloat16* __restrict__ Al,
    const __nv_bfloat16* __restrict__ Bh, const __nv_bfloat16* __restrict__ Bl,
    float* __restrict__ Cm, int M, int N, int K) {
    extern __shared__ __nv_bfloat16 smg[];
    const int tid = threadIdx.x;
    const int lane = tid & 31;
    const int w = tid >> 5;
    const int wm = w & 1;
    const int wn = w >> 1;
    const size_t bm = (size_t)blockIdx.y * 128;
    const size_t bn = (size_t)blockIdx.x * 128;
    const uint32_t sbase = smem_u32(smg);

    float acc[4][4][4];
#pragma unroll
    for (int i = 0; i < 4; i++)
#pragma unroll
        for (int j = 0; j < 4; j++)
#pragma unroll
            for (int q = 0; q < 4; q++) acc[i][j][q] = 0.0f;

    const int NC = K >> 5;

    auto load_stage = [&](int chunk) {
        uint32_t st = sbase + (uint32_t)(chunk & 1) * (GSTAGE * 2);
        const int k0 = chunk << 5;
#pragma unroll
        for (int s = 0; s < 8; s++) {
            int idx = s * 256 + tid;
            int tile = idx >> 9;
            int row = (idx >> 2) & 127;
            int ch = idx & 3;
            uint32_t dst = st + (uint32_t)(tile * GTILE + row * GPITCH + ch * 8) * 2;
            const __nv_bfloat16* src;
            if (tile == 0)      src = Ah + (bm + row) * (size_t)K + k0 + ch * 8;
            else if (tile == 1) src = Al + (bm + row) * (size_t)K + k0 + ch * 8;
            else if (tile == 2) src = Bh + (bn + row) * (size_t)K + k0 + ch * 8;
            else                src = Bl + (bn + row) * (size_t)K + k0 + ch * 8;
            cpa16(dst, src);
        }
        cpa_commit();
    };

    load_stage(0);

    for (int c = 0; c < NC; c++) {
        if (c + 1 < NC) {
            load_stage(c + 1);
            cpa_wait<1>();
        } else {
            cpa_wait<0>();
        }
        __syncthreads();

        uint32_t st = sbase + (uint32_t)(c & 1) * (GSTAGE * 2);
        uint32_t aHh = st;
        uint32_t aLl = st + (uint32_t)GTILE * 2;
        uint32_t bHh = st + (uint32_t)(2 * GTILE) * 2;
        uint32_t bLl = st + (uint32_t)(3 * GTILE) * 2;

#pragma unroll
        for (int ks = 0; ks < 2; ks++) {
            const int k0 = ks * 16;
            uint32_t ah[4][4], al[4][4];
            {
                int mrow = wm * 64 + (lane & 7) + ((lane >> 3) & 1) * 8;
                int kcol = k0 + (lane >> 4) * 8;
                uint32_t off = (uint32_t)(mrow * GPITCH + kcol) * 2;
#pragma unroll
                for (int mi = 0; mi < 4; mi++) {
                    uint32_t ao = off + (uint32_t)(mi * 16 * GPITCH) * 2;
                    ldsm_x4(ah[mi][0], ah[mi][1], ah[mi][2], ah[mi][3], aHh + ao);
                    ldsm_x4(al[mi][0], al[mi][1], al[mi][2], al[mi][3], aLl + ao);
                }
            }
            uint32_t bh[2][4], bl[2][4];
            {
                int nrow = wn * 32 + ((lane >> 4) << 3) + (lane & 7);
                int kcol = k0 + ((lane >> 3) & 1) * 8;
                uint32_t off = (uint32_t)(nrow * GPITCH + kcol) * 2;
#pragma unroll
                for (int p = 0; p < 2; p++) {
                    uint32_t bo = off + (uint32_t)(p * 16 * GPITCH) * 2;
                    ldsm_x4(bh[p][0], bh[p][1], bh[p][2], bh[p][3], bHh + bo);
                    ldsm_x4(bl[p][0], bl[p][1], bl[p][2], bl[p][3], bLl + bo);
                }
            }
#pragma unroll
            for (int mi = 0; mi < 4; mi++)
#pragma unroll
                for (int ni = 0; ni < 4; ni++)
                    mma_bf16(acc[mi][ni], ah[mi], &bh[ni >> 1][(ni & 1) * 2]);
#pragma unroll
            for (int mi = 0; mi < 4; mi++)
#pragma unroll
                for (int ni = 0; ni < 4; ni++)
                    mma_bf16(acc[mi][ni], ah[mi], &bl[ni >> 1][(ni & 1) * 2]);
#pragma unroll
            for (int mi = 0; mi < 4; mi++)
#pragma unroll
                for (int ni = 0; ni < 4; ni++)
                    mma_bf16(acc[mi][ni], al[mi], &bh[ni >> 1][(ni & 1) * 2]);
        }
        __syncthreads();
    }

#pragma unroll
    for (int mi = 0; mi < 4; mi++) {
        int r0 = (int)(bm + wm * 64 + mi * 16 + (lane >> 2));
#pragma unroll
        for (int ni = 0; ni < 4; ni++) {
            int col = (int)(bn + wn * 32 + ni * 8 + 2 * (lane & 3));
            if (EPI == 0) {
                *(float2*)(Cm + (size_t)r0 * N + col) =
                    make_float2(acc[mi][ni][0], acc[mi][ni][1]);
                *(float2*)(Cm + (size_t)(r0 + 8) * N + col) =
                    make_float2(acc[mi][ni][2], acc[mi][ni][3]);
            } else {
                rope_split_store(r0, col, acc[mi][ni][0], acc[mi][ni][1]);
                rope_split_store(r0 + 8, col, acc[mi][ni][2], acc[mi][ni][3]);
            }
        }
    }
}

// ---------------- tensor-core flash attention (causal, GQA) ------------------
// R6 geometry (128 q-rows, 8 warps, KV tile 64) + Q fragments hoisted to regs.
#define FP 136
#define QTILE_E (128 * FP)
#define KVTILE_E (64 * FP)
#define STAGE_E (4 * KVTILE_E)
#define FLASH_SMEM ((2 * QTILE_E + 2 * STAGE_E) * 2)   // 208896 B

__global__ __launch_bounds__(256) void flash_mma() {
    extern __shared__ __nv_bfloat16 fsm[];
    const uint32_t sb = smem_u32(fsm);
    const int tid = threadIdx.x;
    const int lane = tid & 31;
    const int w = tid >> 5;
    const int qt = (int)(gridDim.x - 1 - blockIdx.x);
    const int h = blockIdx.y;
    const int b = blockIdx.z;
    const int kvh = h >> 2;
    const int qbase = qt * 128;
    const int nkv = 2 * qt + 2;

    const __nv_bfloat16* qhp = g_qh + ((size_t)(b * NH + h) * T_ + qbase) * HD_;
    const __nv_bfloat16* qlp = g_ql + ((size_t)(b * NH + h) * T_ + qbase) * HD_;
    const __nv_bfloat16* khp = g_kh + (size_t)(b * NKV + kvh) * T_ * HD_;
    const __nv_bfloat16* klp = g_kl + (size_t)(b * NKV + kvh) * T_ * HD_;
    const __nv_bfloat16* vhp = g_vh + (size_t)(b * NKV + kvh) * T_ * HD_;
    const __nv_bfloat16* vlp = g_vl + (size_t)(b * NKV + kvh) * T_ * HD_;

    // Q tile load (hi+lo), grouped with kv stage 0 commit
#pragma unroll
    for (int s = 0; s < 16; s++) {
        int idx = s * 256 + tid;
        int half = idx >> 11;
        int rem = idx & 2047;
        int row = rem >> 4;
        int ch = rem & 15;
        uint32_t dst = sb + (uint32_t)(half * QTILE_E + row * FP) * 2 + ch * 16;
        const __nv_bfloat16* src = (half ? qlp : qhp) + (size_t)row * HD_ + ch * 8;
        cpa16(dst, src);
    }

    auto load_kv = [&](int ki) {
        int kv0 = ki * 64;
        uint32_t stb = sb + (uint32_t)(2 * QTILE_E + (ki & 1) * STAGE_E) * 2;
#pragma unroll
        for (int s = 0; s < 16; s++) {
            int idx = s * 256 + tid;
            int tile = idx >> 10;
            int rem = idx & 1023;
            int row = rem >> 4;
            int ch = rem & 15;
            uint32_t dst = stb + (uint32_t)(tile * KVTILE_E + row * FP) * 2 + ch * 16;
            const __nv_bfloat16* base =
                (tile == 0) ? khp : (tile == 1) ? klp : (tile == 2) ? vhp : vlp;
            cpa16(dst, base + (size_t)(kv0 + row) * HD_ + ch * 8);
        }
        cpa_commit();
    };

    load_kv(0);   // group 1: Q + kv0
    load_kv(1);   // group 2: kv1

    const int mrow = w * 16 + (lane & 7) + ((lane >> 3) & 1) * 8;
    const int kcA = (lane >> 4) * 8;
    const int nrowK = ((lane >> 4) << 3) + (lane & 7);
    const int kcK = ((lane >> 3) & 1) * 8;
    const int krowV = (lane & 7) + ((lane >> 3) & 1) * 8;
    const int ncV = lane >> 4;
    const int row_in_w = lane >> 2;
    const int rowg0 = qbase + w * 16 + row_in_w;

    // ---- hoist Q fragments (hi+lo) into registers, once
    uint32_t qfh[8][4], qfl[8][4];
    cpa_wait<1>();          // Q + kv0 complete
    __syncthreads();
#pragma unroll
    for (int ks = 0; ks < 8; ks++) {
        uint32_t aoff = (uint32_t)(mrow * FP + ks * 16 + kcA) * 2;
        ldsm_x4(qfh[ks][0], qfh[ks][1], qfh[ks][2], qfh[ks][3], sb + aoff);
        ldsm_x4(qfl[ks][0], qfl[ks][1], qfl[ks][2], qfl[ks][3],
                sb + (uint32_t)QTILE_E * 2 + aoff);
    }

    float O[16][4];
#pragma unroll
    for (int i = 0; i < 16; i++)
#pragma unroll
        for (int c = 0; c < 4; c++) O[i][c] = 0.0f;
    float m_i[2] = {-1e30f, -1e30f};
    float l_i[2] = {0.0f, 0.0f};
    const float scale = 0.08838834764831843f;

    for (int ki = 0; ki < nkv; ki++) {
        if (ki + 1 < nkv) cpa_wait<1>(); else cpa_wait<0>();
        __syncthreads();

        const bool active = (ki * 64 <= qbase + w * 16 + 15);
        if (active) {
            uint32_t stb = sb + (uint32_t)(2 * QTILE_E + (ki & 1) * STAGE_E) * 2;
            uint32_t kh_b = stb;
            uint32_t kl_b = stb + (uint32_t)KVTILE_E * 2;
            uint32_t vh_b = stb + (uint32_t)(2 * KVTILE_E) * 2;
            uint32_t vl_b = stb + (uint32_t)(3 * KVTILE_E) * 2;

            float sacc[8][4];
#pragma unroll
            for (int i = 0; i < 8; i++)
#pragma unroll
                for (int c = 0; c < 4; c++) sacc[i][c] = 0.0f;

#pragma unroll
            for (int ks = 0; ks < 8; ks++) {
                uint32_t kh4[4][4], kl4[4][4];
                uint32_t koff = (uint32_t)(nrowK * FP + ks * 16 + kcK) * 2;
#pragma unroll
                for (int p = 0; p < 4; p++) {
                    uint32_t bo = koff + (uint32_t)(p * 16 * FP) * 2;
                    ldsm_x4(kh4[p][0], kh4[p][1], kh4[p][2], kh4[p][3], kh_b + bo);
                    ldsm_x4(kl4[p][0], kl4[p][1], kl4[p][2], kl4[p][3], kl_b + bo);
                }
#pragma unroll
                for (int p = 0; p < 4; p++) {
                    mma_bf16(sacc[2 * p], qfh[ks], &kh4[p][0]);
                    mma_bf16(sacc[2 * p + 1], qfh[ks], &kh4[p][2]);
                }
#pragma unroll
                for (int p = 0; p < 4; p++) {
                    mma_bf16(sacc[2 * p], qfh[ks], &kl4[p][0]);
                    mma_bf16(sacc[2 * p + 1], qfh[ks], &kl4[p][2]);
                }
#pragma unroll
                for (int p = 0; p < 4; p++) {
                    mma_bf16(sacc[2 * p], qfl[ks], &kh4[p][0]);
                    mma_bf16(sacc[2 * p + 1], qfl[ks], &kh4[p][2]);
                }
            }

            const int kv0 = ki * 64;
            if (ki >= 2 * qt) {
#pragma unroll
                for (int ni = 0; ni < 8; ni++)
#pragma unroll
                    for (int c = 0; c < 4; c++) {
                        int colg = kv0 + ni * 8 + 2 * (lane & 3) + (c & 1);
                        int rowg = rowg0 + ((c >> 1) << 3);
                        sacc[ni][c] = (colg <= rowg) ? sacc[ni][c] * scale : -1e30f;
                    }
            } else {
#pragma unroll
                for (int ni = 0; ni < 8; ni++)
#pragma unroll
                    for (int c = 0; c < 4; c++) sacc[ni][c] *= scale;
            }

            float mx0 = -1e30f, mx1 = -1e30f;
#pragma unroll
            for (int ni = 0; ni < 8; ni++) {
                mx0 = fmaxf(mx0, fmaxf(sacc[ni][0], sacc[ni][1]));
                mx1 = fmaxf(mx1, fmaxf(sacc[ni][2], sacc[ni][3]));
            }
#pragma unroll
            for (int off = 1; off <= 2; off <<= 1) {
                mx0 = fmaxf(mx0, __shfl_xor_sync(0xffffffffu, mx0, off));
                mx1 = fmaxf(mx1, __shfl_xor_sync(0xffffffffu, mx1, off));
            }
            float mn0 = fmaxf(m_i[0], mx0);
            float mn1 = fmaxf(m_i[1], mx1);
            float cr0 = __expf(m_i[0] - mn0);
            float cr1 = __expf(m_i[1] - mn1);
            m_i[0] = mn0; m_i[1] = mn1;
            float sm0 = 0.0f, sm1 = 0.0f;
#pragma unroll
            for (int ni = 0; ni < 8; ni++) {
                float p0 = __expf(sacc[ni][0] - mn0);
                float p1 = __expf(sacc[ni][1] - mn0);
                float p2 = __expf(sacc[ni][2] - mn1);
                float p3 = __expf(sacc[ni][3] - mn1);
                sacc[ni][0] = p0; sacc[ni][1] = p1;
                sacc[ni][2] = p2; sacc[ni][3] = p3;
                sm0 += p0 + p1;
                sm1 += p2 + p3;
            }
#pragma unroll
            for (int off = 1; off <= 2; off <<= 1) {
                sm0 += __shfl_xor_sync(0xffffffffu, sm0, off);
                sm1 += __shfl_xor_sync(0xffffffffu, sm1, off);
            }
            l_i[0] = l_i[0] * cr0 + sm0;
            l_i[1] = l_i[1] * cr1 + sm1;
#pragma unroll
            for (int ni = 0; ni < 16; ni++) {
                O[ni][0] *= cr0; O[ni][1] *= cr0;
                O[ni][2] *= cr1; O[ni][3] *= cr1;
            }

#pragma unroll
            for (int kt = 0; kt < 4; kt++) {
                uint32_t aP[4], aPl[4];
                {
                    float p0 = sacc[2 * kt][0], p1 = sacc[2 * kt][1];
                    float p2 = sacc[2 * kt][2], p3 = sacc[2 * kt][3];
                    float q0 = sacc[2 * kt + 1][0], q1 = sacc[2 * kt + 1][1];
                    float q2 = sacc[2 * kt + 1][2], q3 = sacc[2 * kt + 1][3];
                    aP[0] = packbf(p0, p1);
                    aP[1] = packbf(p2, p3);
                    aP[2] = packbf(q0, q1);
                    aP[3] = packbf(q2, q3);
                    aPl[0] = packbf(p0 - bflo(aP[0]), p1 - bfhi(aP[0]));
                    aPl[1] = packbf(p2 - bflo(aP[1]), p3 - bfhi(aP[1]));
                    aPl[2] = packbf(q0 - bflo(aP[2]), q1 - bfhi(aP[2]));
                    aPl[3] = packbf(q2 - bflo(aP[3]), q3 - bfhi(aP[3]));
                }
#pragma unroll
                for (int g = 0; g < 4; g++) {
                    uint32_t vh0[4], vl0[4], vh1[4], vl1[4];
                    uint32_t voff0 =
                        (uint32_t)((kt * 16 + krowV) * FP + (4 * g + ncV) * 8) * 2;
                    uint32_t voff1 =
                        (uint32_t)((kt * 16 + krowV) * FP + (4 * g + 2 + ncV) * 8) * 2;
                    ldsm_x4_t(vh0[0], vh0[1], vh0[2], vh0[3], vh_b + voff0);
                    ldsm_x4_t(vl0[0], vl0[1], vl0[2], vl0[3], vl_b + voff0);
                    ldsm_x4_t(vh1[0], vh1[1], vh1[2], vh1[3], vh_b + voff1);
                    ldsm_x4_t(vl1[0], vl1[1], vl1[2], vl1[3], vl_b + voff1);
                    mma_bf16(O[4 * g + 0], aP, vh0);
                    mma_bf16(O[4 * g + 1], aP, vh0 + 2);
                    mma_bf16(O[4 * g + 2], aP, vh1);
                    mma_bf16(O[4 * g + 3], aP, vh1 + 2);
                    mma_bf16(O[4 * g + 0], aP, vl0);
                    mma_bf16(O[4 * g + 1], aP, vl0 + 2);
                    mma_bf16(O[4 * g + 2], aP, vl1);
                    mma_bf16(O[4 * g + 3], aP, vl1 + 2);
                    mma_bf16(O[4 * g + 0], aPl, vh0);
                    mma_bf16(O[4 * g + 1], aPl, vh0 + 2);
                    mma_bf16(O[4 * g + 2], aPl, vh1);
                    mma_bf16(O[4 * g + 3], aPl, vh1 + 2);
                }
            }
        }
        __syncthreads();
        if (ki + 2 < nkv) load_kv(ki + 2);
    }

    // ---- epilogue: O / l -> bf16 hi/lo (g_yh, g_yl) directly
    float inv0 = 1.0f / l_i[0];
    float inv1 = 1.0f / l_i[1];
    const int rg0 = qbase + w * 16 + row_in_w;
#pragma unroll
    for (int ni = 0; ni < 16; ni++) {
        int col = h * HD_ + ni * 8 + 2 * (lane & 3);
        size_t o0 = ((size_t)b * T_ + rg0) * C_ + col;
        size_t o1 = ((size_t)b * T_ + rg0 + 8) * C_ + col;
        float v0 = O[ni][0] * inv0, v1 = O[ni][1] * inv0;
        float v2 = O[ni][2] * inv1, v3 = O[ni][3] * inv1;
        __nv_bfloat16 h0 = __float2bfloat16_rn(v0);
        __nv_bfloat16 h1 = __float2bfloat16_rn(v1);
        __nv_bfloat16 h2 = __float2bfloat16_rn(v2);
        __nv_bfloat16 h3 = __float2bfloat16_rn(v3);
        *(__nv_bfloat162*)(g_yh + o0) = __halves2bfloat162(h0, h1);
        *(__nv_bfloat162*)(g_yh + o1) = __halves2bfloat162(h2, h3);
        *(__nv_bfloat162*)(g_yl + o0) = __halves2bfloat162(
            __float2bfloat16_rn(v0 - __bfloat162float(h0)),
            __float2bfloat16_rn(v1 - __bfloat162float(h1)));
        *(__nv_bfloat162*)(g_yl + o1) = __halves2bfloat162(
            __float2bfloat16_rn(v2 - __bfloat162float(h2)),
            __float2bfloat16_rn(v3 - __bfloat162float(h3)));
    }
}

// ---------------- driver ----------------------------------------------------
extern "C" void kernel_launch(void* const* d_in, const int* in_sizes, int n_in,
                              void* d_out, int out_size) {
    const float* x = nullptr;
    const float* w_attn = nullptr;
    const float* w_proj = nullptr;
    for (int i = 0; i < n_in; i++) {
        if (in_sizes[i] == B_ * T_ * C_) x = (const float*)d_in[i];
        else if (in_sizes[i] == QKVD * C_) w_attn = (const float*)d_in[i];
        else if (in_sizes[i] == C_ * C_) w_proj = (const float*)d_in[i];
    }
    float* out = (float*)d_out;

    __nv_bfloat16 *xh, *xl, *yh, *yl, *wah, *wal, *wph, *wpl;
    cudaGetSymbolAddress((void**)&xh, g_xh);
    cudaGetSymbolAddress((void**)&xl, g_xl);
    cudaGetSymbolAddress((void**)&yh, g_yh);
    cudaGetSymbolAddress((void**)&yl, g_yl);
    cudaGetSymbolAddress((void**)&wah, g_wah);
    cudaGetSymbolAddress((void**)&wal, g_wal);
    cudaGetSymbolAddress((void**)&wph, g_wph);
    cudaGetSymbolAddress((void**)&wpl, g_wpl);

    cudaFuncSetAttribute(gemm_mma<0>, cudaFuncAttributeMaxDynamicSharedMemorySize,
                         GEMM_SMEM);
    cudaFuncSetAttribute(gemm_mma<1>, cudaFuncAttributeMaxDynamicSharedMemorySize,
                         GEMM_SMEM);
    cudaFuncSetAttribute(flash_mma, cudaFuncAttributeMaxDynamicSharedMemorySize,
                         FLASH_SMEM);

    // 1: RoPE table
    rope_table_kernel<<<(T_ * 64 + 255) / 256, 256>>>();

    // 2: combined splits (x, w_attn, w_proj)
    {
        int total = NX4 + NWA4 + NWP4;
        split_all_kernel<<<(total + 255) / 256, 256>>>(x, w_attn, w_proj);
    }

    // 3: GEMM1 (fused RoPE/split/scatter epilogue)
    {
        dim3 grid(QKVD / 128, (B_ * T_) / 128);
        gemm_mma<1><<<grid, 256, GEMM_SMEM>>>(xh, xl, wah, wal, nullptr,
                                              B_ * T_, QKVD, C_);
    }

    // 4: tensor-core flash attention -> g_yh/g_yl  (ncu capture slot)
    {
        dim3 grid(T_ / 128, NH, B_);
        flash_mma<<<grid, 256, FLASH_SMEM>>>();
    }

    // 5: GEMM2: out = y @ w_proj^T
    {
        dim3 grid(C_ / 128, (B_ * T_) / 128);
        gemm_mma<0><<<grid, 256, GEMM_SMEM>>>(yh, yl, wph, wpl, out,
                                              B_ * T_, C_, C_);
    }
}